// round 8
// baseline (speedup 1.0000x reference)
#include <cuda_runtime.h>
#include <math.h>
#include <stdint.h>

#define N0C 50000
#define E0C 800000
#define N1C 10000
#define E1C 160000
#define FC  128
#define HC  256
#define BC  64

// ---------------- static scratch ----------------
__device__ float g_xw [N0C * HC];
__device__ float g_x1 [N0C * HC];
__device__ float g_x2 [N0C * HC];
__device__ float g_h  [N0C * HC];
__device__ float g_dinv0[N0C];

__device__ float g_h1cat[N1C * 2 * HC];
__device__ float g_yw [N1C * HC];
__device__ float g_y1 [N1C * HC];
__device__ float g_y2 [N1C * HC];
__device__ float g_hb [N1C * HC];
__device__ float g_dinv1[N1C];

__device__ float g_z [BC * 4 * HC];

// paired bf16x2 hi/lo operand arrays (word = bf16x2 of k=2kp,2kp+1)
__device__ uint32_t g_xp_h [N0C * FC / 2];
__device__ uint32_t g_xp_l [N0C * FC / 2];
__device__ uint32_t g_x1p_h[N0C * HC / 2];
__device__ uint32_t g_x1p_l[N0C * HC / 2];
__device__ uint32_t g_x2p_h[N0C * HC / 2];
__device__ uint32_t g_x2p_l[N0C * HC / 2];
__device__ uint32_t g_h1p_h[N1C * HC];       // 2H/2 = H words per row
__device__ uint32_t g_h1p_l[N1C * HC];
__device__ uint32_t g_y1p_h[N1C * HC / 2];
__device__ uint32_t g_y1p_l[N1C * HC / 2];
__device__ uint32_t g_y2p_h[N1C * HC / 2];
__device__ uint32_t g_y2p_l[N1C * HC / 2];
// weight pair arrays [K/2][256]
__device__ uint32_t g_w0p_h [64 * HC],  g_w0p_l [64 * HC];
__device__ uint32_t g_w1p_h [128 * HC], g_w1p_l [128 * HC];
__device__ uint32_t g_wjp_h [256 * HC], g_wjp_l [256 * HC];
__device__ uint32_t g_wb0p_h[256 * HC], g_wb0p_l[256 * HC];
__device__ uint32_t g_wb1p_h[128 * HC], g_wb1p_l[128 * HC];
__device__ uint32_t g_wjbp_h[256 * HC], g_wjbp_l[256 * HC];

// ---------------- split helpers ----------------
__device__ __forceinline__ void split_pair(float fx, float fy,
                                           uint32_t& hi, uint32_t& lo) {
    asm("cvt.rn.bf16x2.f32 %0, %1, %2;" : "=r"(hi) : "f"(fy), "f"(fx));
    float hx = __uint_as_float(hi << 16);
    float hy = __uint_as_float(hi & 0xFFFF0000u);
    float rx = fx - hx;
    float ry = fy - hy;
    asm("cvt.rn.bf16x2.f32 %0, %1, %2;" : "=r"(lo) : "f"(ry), "f"(rx));
}

// ---------------- utility kernels ----------------
__global__ void fill_kernel(float* p, int n, float v) {
    int i = blockIdx.x * blockDim.x + threadIdx.x;
    if (i < n) p[i] = v;
}

__global__ void deg_accum_kernel(const int* __restrict__ col,
                                 const float* __restrict__ ew,
                                 float* __restrict__ deg, int E) {
    int e = blockIdx.x * blockDim.x + threadIdx.x;
    if (e < E) atomicAdd(&deg[col[e]], ew[e]);
}

__global__ void finalize_dinv_kernel(float* deg, int n) {
    int i = blockIdx.x * blockDim.x + threadIdx.x;
    if (i < n) {
        float d = deg[i];
        deg[i] = (d > 0.f) ? rsqrtf(d) : 0.f;
    }
}

// split fp32 [M,F] (F%4==0) into paired hi/lo word arrays [M,F/2]
__global__ void split_pairs_kernel(const float* __restrict__ in,
                                   uint32_t* __restrict__ hi,
                                   uint32_t* __restrict__ lo,
                                   int total4, int doRelu) {
    int g = blockIdx.x * blockDim.x + threadIdx.x;
    if (g >= total4) return;
    float4 v = reinterpret_cast<const float4*>(in)[g];
    if (doRelu) {
        v.x = fmaxf(v.x, 0.f); v.y = fmaxf(v.y, 0.f);
        v.z = fmaxf(v.z, 0.f); v.w = fmaxf(v.w, 0.f);
    }
    uint32_t h0, l0, h1, l1;
    split_pair(v.x, v.y, h0, l0);
    split_pair(v.z, v.w, h1, l1);
    reinterpret_cast<uint2*>(hi)[g] = make_uint2(h0, h1);
    reinterpret_cast<uint2*>(lo)[g] = make_uint2(l0, l1);
}

// split weights [K,N] into k-paired [K/2][N] word arrays
__global__ void split_wpairs_kernel(const float* __restrict__ in,
                                    uint32_t* __restrict__ hi,
                                    uint32_t* __restrict__ lo,
                                    int KP, int N) {
    int idx = blockIdx.x * blockDim.x + threadIdx.x;
    int total = KP * (N / 4);
    if (idx >= total) return;
    int kp = idx / (N / 4);
    int n4 = (idx - kp * (N / 4)) * 4;
    float4 r0 = *reinterpret_cast<const float4*>(in + (size_t)(2 * kp) * N + n4);
    float4 r1 = *reinterpret_cast<const float4*>(in + (size_t)(2 * kp + 1) * N + n4);
    uint32_t h[4], l[4];
    split_pair(r0.x, r1.x, h[0], l[0]);
    split_pair(r0.y, r1.y, h[1], l[1]);
    split_pair(r0.z, r1.z, h[2], l[2]);
    split_pair(r0.w, r1.w, h[3], l[3]);
    *reinterpret_cast<uint4*>(hi + (size_t)kp * N + n4) = make_uint4(h[0], h[1], h[2], h[3]);
    *reinterpret_cast<uint4*>(lo + (size_t)kp * N + n4) = make_uint4(l[0], l[1], l[2], l[3]);
}

// fused first launch: x split + W_in0 split + dinv0 fill
__global__ void prep0_kernel(const float* __restrict__ x,
                             uint32_t* __restrict__ xh, uint32_t* __restrict__ xl,
                             const float* __restrict__ w,
                             uint32_t* __restrict__ wh, uint32_t* __restrict__ wl,
                             float* __restrict__ dinv,
                             int n0, int totalX4, int KPw, int Nw) {
    int i = blockIdx.x * blockDim.x + threadIdx.x;
    if (i < totalX4) {
        float4 v = reinterpret_cast<const float4*>(x)[i];
        uint32_t h0, l0, h1, l1;
        split_pair(v.x, v.y, h0, l0);
        split_pair(v.z, v.w, h1, l1);
        reinterpret_cast<uint2*>(xh)[i] = make_uint2(h0, h1);
        reinterpret_cast<uint2*>(xl)[i] = make_uint2(l0, l1);
    }
    if (i < KPw * (Nw / 4)) {
        int kp = i / (Nw / 4);
        int n4 = (i - kp * (Nw / 4)) * 4;
        float4 r0 = *reinterpret_cast<const float4*>(w + (size_t)(2 * kp) * Nw + n4);
        float4 r1 = *reinterpret_cast<const float4*>(w + (size_t)(2 * kp + 1) * Nw + n4);
        uint32_t h[4], l[4];
        split_pair(r0.x, r1.x, h[0], l[0]);
        split_pair(r0.y, r1.y, h[1], l[1]);
        split_pair(r0.z, r1.z, h[2], l[2]);
        split_pair(r0.w, r1.w, h[3], l[3]);
        *reinterpret_cast<uint4*>(wh + (size_t)kp * Nw + n4) = make_uint4(h[0], h[1], h[2], h[3]);
        *reinterpret_cast<uint4*>(wl + (size_t)kp * Nw + n4) = make_uint4(l[0], l[1], l[2], l[3]);
    }
    if (i < n0) dinv[i] = 1.f;
}

// Edge scatter with vector reductions
__global__ void gcn_scatter_red4(const float* __restrict__ xw,
                                 const int* __restrict__ row,
                                 const int* __restrict__ col,
                                 const float* __restrict__ ew,
                                 const float* __restrict__ dinv,
                                 float* __restrict__ out,
                                 int E, int edgesPerBlock) {
    int f4 = threadIdx.x & 63;
    int es = threadIdx.x >> 6;
    int e0 = blockIdx.x * edgesPerBlock;
    int e1 = e0 + edgesPerBlock;
    if (e1 > E) e1 = E;
    for (int e = e0 + es; e < e1; e += 4) {
        int r = row[e], c = col[e];
        float coef = dinv[r] * ew[e] * dinv[c];
        float4 v = *reinterpret_cast<const float4*>(xw + (size_t)r * HC + f4 * 4);
        float* dst = out + (size_t)c * HC + f4 * 4;
        asm volatile("red.global.add.v4.f32 [%0], {%1, %2, %3, %4};"
                     :: "l"(dst),
                        "f"(coef * v.x), "f"(coef * v.y),
                        "f"(coef * v.z), "f"(coef * v.w)
                     : "memory");
    }
}

// ---------------- bf16 3-term tensor-core GEMM, pre-split operands --------
#define GBM 128
#define GBN 128
#define S_AHI 0
#define S_ALO 1024
#define S_BHI 2048
#define S_BLO 3072
#define S_BUF 4096

__device__ __forceinline__ void mma_bf16(float* c, const uint32_t* a, const uint32_t* b) {
    asm volatile(
        "mma.sync.aligned.m16n8k16.row.col.f32.bf16.bf16.f32 "
        "{%0,%1,%2,%3}, {%4,%5,%6,%7}, {%8,%9}, {%0,%1,%2,%3};"
        : "+f"(c[0]), "+f"(c[1]), "+f"(c[2]), "+f"(c[3])
        : "r"(a[0]), "r"(a[1]), "r"(a[2]), "r"(a[3]), "r"(b[0]), "r"(b[1]));
}

__device__ __forceinline__ int a_swz(int lin) {
    return lin ^ (((lin >> 5) & 3) << 2);
}

// A operands: paired word arrays A1h/A1l [M,KP1], A2h/A2l [M,KP-KP1].
// W operand: paired [KP][N] word arrays. KP in kpair (=2 floats) units.
__global__ __launch_bounds__(256, 2)
void gemm_bf16_kernel(const uint32_t* __restrict__ A1h, const uint32_t* __restrict__ A1l,
                      const uint32_t* __restrict__ A2h, const uint32_t* __restrict__ A2l,
                      int KP1, int KP,
                      const uint32_t* __restrict__ Wh, const uint32_t* __restrict__ Wl,
                      const float* __restrict__ bias,
                      float* __restrict__ C,
                      float* __restrict__ C2,
                      const float* __restrict__ dinv,
                      int M, int N, int reluOut) {
    extern __shared__ uint32_t smem[];

    const int tid  = threadIdx.x;
    const int lane = tid & 31;
    const int warp = tid >> 5;
    const int warp_m = warp & 1;
    const int warp_n = warp >> 1;
    const int bm = blockIdx.y * GBM;
    const int bn = blockIdx.x * GBN;
    const int KP2 = KP - KP1;

    // A staging: thread handles row am, 4 kpairs starting at (tid&1)*4
    const int am     = tid >> 1;
    const int apb    = (tid & 1) * 4;
    const int amtile = am >> 4;
    const int ar     = am & 15;
    const int abase  = amtile * 128 + (ar & 7) * 16 + (ar >> 3);

    // B staging: thread handles kpair bkp, 4 cols at bn0
    const int bkp  = tid >> 5;
    const int bn0  = (tid & 31) * 4;
    const int bkt  = (bkp & 3) * 2 + (bkp >> 2);

    float c[4][4][4];
#pragma unroll
    for (int mi = 0; mi < 4; mi++)
#pragma unroll
        for (int ni = 0; ni < 4; ni++)
#pragma unroll
            for (int q = 0; q < 4; q++) c[mi][ni][q] = 0.f;

    const int nt = KP / 8;   // 8 kpairs (=16 k) per tile

    uint4 vah, val, vwh, vwl;
    auto LOAD_TILE = [&](int t) {
        int kpb = t * 8 + apb;
        int gm = bm + am;
        vah = make_uint4(0, 0, 0, 0);
        val = make_uint4(0, 0, 0, 0);
        if (gm < M) {
            if (kpb < KP1) {
                size_t off = (size_t)gm * KP1 + kpb;
                vah = *reinterpret_cast<const uint4*>(A1h + off);
                val = *reinterpret_cast<const uint4*>(A1l + off);
            } else {
                size_t off = (size_t)gm * KP2 + (kpb - KP1);
                vah = *reinterpret_cast<const uint4*>(A2h + off);
                val = *reinterpret_cast<const uint4*>(A2l + off);
            }
        }
        size_t woff = (size_t)(t * 8 + bkp) * N + bn + bn0;
        vwh = *reinterpret_cast<const uint4*>(Wh + woff);
        vwl = *reinterpret_cast<const uint4*>(Wl + woff);
    };

    auto STORE_TILE = [&](int buf) {
        uint32_t* sb = smem + buf * S_BUF;
        uint32_t ah[4] = {vah.x, vah.y, vah.z, vah.w};
        uint32_t al[4] = {val.x, val.y, val.z, val.w};
#pragma unroll
        for (int j = 0; j < 4; j++) {
            int p = apb + j;
            int lin = abase + (p & 3) * 4 + (p >> 2) * 2;
            int sw = a_swz(lin);
            sb[S_AHI + sw] = ah[j];
            sb[S_ALO + sw] = al[j];
        }
        uint32_t wh[4] = {vwh.x, vwh.y, vwh.z, vwh.w};
        uint32_t wl[4] = {vwl.x, vwl.y, vwl.z, vwl.w};
#pragma unroll
        for (int q = 0; q < 4; q++) {
            int n = bn0 + q;
            int ntile = n >> 3;
            int lin = ntile * 64 + (n & 7) * 8 + bkt;
            int sw = lin ^ ((ntile & 15) << 1);
            sb[S_BHI + sw] = wh[q];
            sb[S_BLO + sw] = wl[q];
        }
    };

    LOAD_TILE(0);
    STORE_TILE(0);
    __syncthreads();

    int cur = 0;
    for (int t = 0; t < nt; t++) {
        const bool more = (t + 1 < nt);
        if (more) LOAD_TILE(t + 1);

        const uint32_t* sb = smem + cur * S_BUF;

        uint32_t bh[4][2], bl[4][2];
#pragma unroll
        for (int ni = 0; ni < 4; ni++) {
            int ntile = warp_n * 4 + ni;
            int lin = ntile * 64 + lane * 2;
            int sw = lin ^ ((ntile & 15) << 1);
            uint2 h = *reinterpret_cast<const uint2*>(sb + S_BHI + sw);
            uint2 l = *reinterpret_cast<const uint2*>(sb + S_BLO + sw);
            bh[ni][0] = h.x; bh[ni][1] = h.y;
            bl[ni][0] = l.x; bl[ni][1] = l.y;
        }

#pragma unroll
        for (int mi = 0; mi < 4; mi++) {
            int mtile = warp_m * 4 + mi;
            int lin = mtile * 128 + lane * 4;
            int sw = a_swz(lin);
            uint4 h4 = *reinterpret_cast<const uint4*>(sb + S_AHI + sw);
            uint4 l4 = *reinterpret_cast<const uint4*>(sb + S_ALO + sw);
            uint32_t ah[4] = {h4.x, h4.y, h4.z, h4.w};
            uint32_t al[4] = {l4.x, l4.y, l4.z, l4.w};
#pragma unroll
            for (int ni = 0; ni < 4; ni++) {
                mma_bf16(c[mi][ni], ah, bh[ni]);
                mma_bf16(c[mi][ni], ah, bl[ni]);
                mma_bf16(c[mi][ni], al, bh[ni]);
            }
        }

        if (more) {
            STORE_TILE(cur ^ 1);
            __syncthreads();
            cur ^= 1;
        }
    }

    // ---- epilogue ----
    const int gid = lane >> 2;
    const int tig = lane & 3;
#pragma unroll
    for (int mi = 0; mi < 4; mi++) {
#pragma unroll
        for (int half = 0; half < 2; half++) {
            int gm = bm + warp_m * 64 + mi * 16 + gid + half * 8;
            if (gm >= M) continue;
            float dd = 0.f;
            if (C2) { float dv = dinv[gm]; dd = dv * dv; }
#pragma unroll
            for (int ni = 0; ni < 4; ni++) {
                int gn = bn + warp_n * 32 + ni * 8 + tig * 2;
                float v0 = c[mi][ni][half * 2 + 0];
                float v1 = c[mi][ni][half * 2 + 1];
                if (C2) {
                    *reinterpret_cast<float2*>(C + (size_t)gm * N + gn) =
                        make_float2(v0, v1);
                    float b0 = bias[gn], b1 = bias[gn + 1];
                    *reinterpret_cast<float2*>(C2 + (size_t)gm * N + gn) =
                        make_float2(b0 + dd * v0, b1 + dd * v1);
                } else {
                    if (bias) { v0 += bias[gn]; v1 += bias[gn + 1]; }
                    if (reluOut) { v0 = fmaxf(v0, 0.f); v1 = fmaxf(v1, 0.f); }
                    *reinterpret_cast<float2*>(C + (size_t)gm * N + gn) =
                        make_float2(v0, v1);
                }
            }
        }
    }
}

// ---------------- segment pool (sum + max), values >= 0 -----------
__global__ void segpool_kernel(const float* __restrict__ in,
                               const int* __restrict__ gatherIdx,
                               const int* __restrict__ seg,
                               int M, int F,
                               float* __restrict__ outSum,
                               float* __restrict__ outMax,
                               int ldOut, int nodesPerBlock) {
    int f = threadIdx.x;
    int n0 = blockIdx.x * nodesPerBlock;
    int n1 = n0 + nodesPerBlock;
    if (n1 > M) n1 = M;
    if (n0 >= n1) return;
    int cur = seg[n0];
    float s = 0.f, mx = 0.f;
    for (int n = n0; n < n1; n++) {
        int sg = seg[n];
        if (sg != cur) {
            atomicAdd(&outSum[cur * ldOut + f], s);
            atomicMax((int*)&outMax[cur * ldOut + f], __float_as_int(mx));
            s = 0.f; mx = 0.f; cur = sg;
        }
        int rowi = gatherIdx ? gatherIdx[n] : n;
        float v = in[(size_t)rowi * F + f];
        s += v;
        mx = fmaxf(mx, v);
    }
    atomicAdd(&outSum[cur * ldOut + f], s);
    atomicMax((int*)&outMax[cur * ldOut + f], __float_as_int(mx));
}

// ---------------- head ----------------
__global__ void head_kernel(const float* __restrict__ z,
                            const float* __restrict__ gamma,
                            const float* __restrict__ beta,
                            const float* __restrict__ mean,
                            const float* __restrict__ var,
                            const float* __restrict__ W1,
                            const float* __restrict__ b1,
                            const float* __restrict__ W2,
                            const float* __restrict__ b2,
                            float* __restrict__ out) {
    __shared__ float zn[4 * HC];
    __shared__ float s1[HC];
    __shared__ float logits[16];
    int b = blockIdx.x;
    int t = threadIdx.x;
    for (int k = t; k < 4 * HC; k += 256) {
        float v = z[b * 4 * HC + k];
        zn[k] = (v - mean[k]) * rsqrtf(var[k] + 1e-5f) * gamma[k] + beta[k];
    }
    __syncthreads();
    float acc = b1[t];
    for (int k = 0; k < 4 * HC; k++) acc += zn[k] * W1[k * HC + t];
    s1[t] = fmaxf(acc, 0.f);
    __syncthreads();
    if (t < 10) {
        float a2 = b2[t];
        for (int k = 0; k < HC; k++) a2 += s1[k] * W2[k * 10 + t];
        logits[t] = a2;
    }
    __syncthreads();
    if (t == 0) {
        float mx = logits[0];
        for (int c = 1; c < 10; c++) mx = fmaxf(mx, logits[c]);
        float e[10], sum = 0.f;
        for (int c = 0; c < 10; c++) { e[c] = expf(logits[c] - mx); sum += e[c]; }
        float inv = 1.f / sum;
        for (int c = 0; c < 10; c++) out[b * 10 + c] = e[c] * inv;
    }
}

// ---------------- orchestration ----------------
static inline int ceil_div(int a, int b) { return (a + b - 1) / b; }
#define GEMM_SMEM (2 * S_BUF * (int)sizeof(uint32_t))

extern "C" void kernel_launch(void* const* d_in, const int* in_sizes, int n_in,
                              void* d_out, int out_size) {
    const float* x      = (const float*)d_in[0];
    const int*   ei0    = (const int*)d_in[1];
    const float* ew0    = (const float*)d_in[2];
    const int*   batch0 = (const int*)d_in[3];
    const int*   cover  = (const int*)d_in[4];
    const int*   ei1    = (const int*)d_in[5];
    const float* ew1    = (const float*)d_in[6];
    const int*   batch1 = (const int*)d_in[7];
    const float* W_in0  = (const float*)d_in[8];
    const float* b_in0  = (const float*)d_in[9];
    const float* W_in1  = (const float*)d_in[10];
    const float* b_in1  = (const float*)d_in[11];
    const float* W_jk_in= (const float*)d_in[12];
    const float* b_jk_in= (const float*)d_in[13];
    const float* W_b0   = (const float*)d_in[14];
    const float* b_b0   = (const float*)d_in[15];
    const float* W_b1   = (const float*)d_in[16];
    const float* b_b1   = (const float*)d_in[17];
    const float* W_jk_b = (const float*)d_in[18];
    const float* b_jk_b = (const float*)d_in[19];
    const float* bn_g   = (const float*)d_in[20];
    const float* bn_b   = (const float*)d_in[21];
    const float* bn_m   = (const float*)d_in[22];
    const float* bn_v   = (const float*)d_in[23];
    const float* W_lin1 = (const float*)d_in[24];
    const float* b_lin1 = (const float*)d_in[25];
    const float* W_lin2 = (const float*)d_in[26];
    const float* b_lin2 = (const float*)d_in[27];
    float* out = (float*)d_out;

    const int N0 = in_sizes[3];
    const int E0 = in_sizes[2];
    const int N1 = in_sizes[7];
    const int E1 = in_sizes[6];
    const int H = HC;

    const int* row0 = ei0;
    const int* col0 = ei0 + E0;
    const int* nodeC = cover;
    const int* clusC = cover + N0;
    const int* row1 = ei1;
    const int* col1 = ei1 + E1;

    float *xw, *x1, *x2, *h, *dinv0, *h1cat, *yw, *y1, *y2, *hb, *dinv1, *z;
    cudaGetSymbolAddress((void**)&xw, g_xw);
    cudaGetSymbolAddress((void**)&x1, g_x1);
    cudaGetSymbolAddress((void**)&x2, g_x2);
    cudaGetSymbolAddress((void**)&h,  g_h);
    cudaGetSymbolAddress((void**)&dinv0, g_dinv0);
    cudaGetSymbolAddress((void**)&h1cat, g_h1cat);
    cudaGetSymbolAddress((void**)&yw, g_yw);
    cudaGetSymbolAddress((void**)&y1, g_y1);
    cudaGetSymbolAddress((void**)&y2, g_y2);
    cudaGetSymbolAddress((void**)&hb, g_hb);
    cudaGetSymbolAddress((void**)&dinv1, g_dinv1);
    cudaGetSymbolAddress((void**)&z,  g_z);

    uint32_t *xph, *xpl, *x1ph, *x1pl, *x2ph, *x2pl, *h1ph, *h1pl;
    uint32_t *y1ph, *y1pl, *y2ph, *y2pl;
    uint32_t *w0h, *w0l, *w1h, *w1l, *wjh, *wjl, *wb0h, *wb0l, *wb1h, *wb1l, *wjbh, *wjbl;
    cudaGetSymbolAddress((void**)&xph, g_xp_h);   cudaGetSymbolAddress((void**)&xpl, g_xp_l);
    cudaGetSymbolAddress((void**)&x1ph, g_x1p_h); cudaGetSymbolAddress((void**)&x1pl, g_x1p_l);
    cudaGetSymbolAddress((void**)&x2ph, g_x2p_h); cudaGetSymbolAddress((void**)&x2pl, g_x2p_l);
    cudaGetSymbolAddress((void**)&h1ph, g_h1p_h); cudaGetSymbolAddress((void**)&h1pl, g_h1p_l);
    cudaGetSymbolAddress((void**)&y1ph, g_y1p_h); cudaGetSymbolAddress((void**)&y1pl, g_y1p_l);
    cudaGetSymbolAddress((void**)&y2ph, g_y2p_h); cudaGetSymbolAddress((void**)&y2pl, g_y2p_l);
    cudaGetSymbolAddress((void**)&w0h, g_w0p_h);   cudaGetSymbolAddress((void**)&w0l, g_w0p_l);
    cudaGetSymbolAddress((void**)&w1h, g_w1p_h);   cudaGetSymbolAddress((void**)&w1l, g_w1p_l);
    cudaGetSymbolAddress((void**)&wjh, g_wjp_h);   cudaGetSymbolAddress((void**)&wjl, g_wjp_l);
    cudaGetSymbolAddress((void**)&wb0h, g_wb0p_h); cudaGetSymbolAddress((void**)&wb0l, g_wb0p_l);
    cudaGetSymbolAddress((void**)&wb1h, g_wb1p_h); cudaGetSymbolAddress((void**)&wb1l, g_wb1p_l);
    cudaGetSymbolAddress((void**)&wjbh, g_wjbp_h); cudaGetSymbolAddress((void**)&wjbl, g_wjbp_l);

    cudaFuncSetAttribute(gemm_bf16_kernel,
                         cudaFuncAttributeMaxDynamicSharedMemorySize, GEMM_SMEM);

    dim3 gemmBlk(256);
    dim3 g0(H / GBN, ceil_div(N0, GBM));
    dim3 g1(H / GBN, ceil_div(N1, GBM));

    // 1: fused x-split + W_in0-split + dinv0 fill
    {
        int totalX4 = N0 * FC / 4;
        prep0_kernel<<<ceil_div(totalX4, 256), 256>>>(x, xph, xpl, W_in0, w0h, w0l,
                                                      dinv0, N0, totalX4, FC / 2, H);
    }
    deg_accum_kernel<<<ceil_div(E0, 256), 256>>>(col0, ew0, dinv0, E0);      // 2
    finalize_dinv_kernel<<<ceil_div(N0, 256), 256>>>(dinv0, N0);             // 3

    // 4 (profiled): level-0 GCN1 GEMM (xw = x@W, x1 = b + dinv^2*xw)
    gemm_bf16_kernel<<<g0, gemmBlk, GEMM_SMEM>>>(xph, xpl, xph, xpl, FC / 2, FC / 2,
                                                 w0h, w0l, b_in0, xw, x1, dinv0,
                                                 N0, H, 0);
    gcn_scatter_red4<<<ceil_div(E0, 16), 256>>>(xw, row0, col0, ew0, dinv0, x1, E0, 16);

    // remaining weight splits + level-1 dinv + zero fills
    split_wpairs_kernel<<<ceil_div(128 * (H / 4), 256), 256>>>(W_in1, w1h, w1l, 128, H);
    split_wpairs_kernel<<<ceil_div(256 * (H / 4), 256), 256>>>(W_jk_in, wjh, wjl, 256, H);
    split_wpairs_kernel<<<ceil_div(256 * (H / 4), 256), 256>>>(W_b0, wb0h, wb0l, 256, H);
    split_wpairs_kernel<<<ceil_div(128 * (H / 4), 256), 256>>>(W_b1, wb1h, wb1l, 128, H);
    split_wpairs_kernel<<<ceil_div(256 * (H / 4), 256), 256>>>(W_jk_b, wjbh, wjbl, 256, H);
    fill_kernel<<<ceil_div(N1, 256), 256>>>(dinv1, N1, 1.f);
    deg_accum_kernel<<<ceil_div(E1, 256), 256>>>(col1, ew1, dinv1, E1);
    finalize_dinv_kernel<<<ceil_div(N1, 256), 256>>>(dinv1, N1);
    fill_kernel<<<ceil_div(BC * 4 * H, 256), 256>>>(z, BC * 4 * H, 0.f);
    fill_kernel<<<ceil_div(N1 * 2 * H, 256), 256>>>(h1cat, N1 * 2 * H, 0.f);

    // ---- level 0: GCN 2 ----
    split_pairs_kernel<<<ceil_div(N0 * H / 4, 256), 256>>>(x1, x1ph, x1pl, N0 * H / 4, 1);
    gemm_bf16_kernel<<<g0, gemmBlk, GEMM_SMEM>>>(x1ph, x1pl, x1ph, x1pl, H / 2, H / 2,
                                                 w1h, w1l, b_in1, xw, x2, dinv0,
                                                 N0, H, 0);
    gcn_scatter_red4<<<ceil_div(E0, 16), 256>>>(xw, row0, col0, ew0, dinv0, x2, E0, 16);

    // ---- level 0: JK cat + linear + relu ----
    split_pairs_kernel<<<ceil_div(N0 * H / 4, 256), 256>>>(x2, x2ph, x2pl, N0 * H / 4, 1);
    gemm_bf16_kernel<<<g0, gemmBlk, GEMM_SMEM>>>(x1ph, x1pl, x2ph, x2pl, H / 2, H,
                                                 wjh, wjl, b_jk_in, h, NULL, NULL,
                                                 N0, H, 1);

    // ---- pools ----
    segpool_kernel<<<ceil_div(N0, 128), 256>>>(h, NULL, batch0, N0, H,
                                               z + 0, z + H, 4 * H, 128);
    segpool_kernel<<<ceil_div(N0, 128), 256>>>(h, nodeC, clusC, N0, H,
                                               h1cat + 0, h1cat + H, 2 * H, 128);

    // ---- level 1: GCN 1 ----
    split_pairs_kernel<<<ceil_div(N1 * 2 * H / 4, 256), 256>>>(h1cat, h1ph, h1pl,
                                                               N1 * 2 * H / 4, 0);
    gemm_bf16_kernel<<<g1, gemmBlk, GEMM_SMEM>>>(h1ph, h1pl, h1ph, h1pl, H, H,
                                                 wb0h, wb0l, b_b0, yw, y1, dinv1,
                                                 N1, H, 0);
    gcn_scatter_red4<<<ceil_div(E1, 16), 256>>>(yw, row1, col1, ew1, dinv1, y1, E1, 16);

    // ---- level 1: GCN 2 ----
    split_pairs_kernel<<<ceil_div(N1 * H / 4, 256), 256>>>(y1, y1ph, y1pl, N1 * H / 4, 1);
    gemm_bf16_kernel<<<g1, gemmBlk, GEMM_SMEM>>>(y1ph, y1pl, y1ph, y1pl, H / 2, H / 2,
                                                 wb1h, wb1l, b_b1, yw, y2, dinv1,
                                                 N1, H, 0);
    gcn_scatter_red4<<<ceil_div(E1, 16), 256>>>(yw, row1, col1, ew1, dinv1, y2, E1, 16);

    // ---- level 1: JK ----
    split_pairs_kernel<<<ceil_div(N1 * H / 4, 256), 256>>>(y2, y2ph, y2pl, N1 * H / 4, 1);
    gemm_bf16_kernel<<<g1, gemmBlk, GEMM_SMEM>>>(y1ph, y1pl, y2ph, y2pl, H / 2, H,
                                                 wjbh, wjbl, b_jk_b, hb, NULL, NULL,
                                                 N1, H, 1);

    // ---- level-1 batch pool ----
    segpool_kernel<<<ceil_div(N1, 128), 256>>>(hb, NULL, batch1, N1, H,
                                               z + 2 * H, z + 3 * H, 4 * H, 128);

    // ---- head ----
    head_kernel<<<BC, 256>>>(z, bn_g, bn_b, bn_m, bn_v,
                             W_lin1, b_lin1, W_lin2, b_lin2, out);
}